// round 4
// baseline (speedup 1.0000x reference)
#include <cuda_runtime.h>
#include <cuda_bf16.h>

// ---------------------------------------------------------------------------
// GraphSAGE: 2x (SAGEConv -> BN(train stats) -> ReLU) -> Linear[128->2]
// Strategy:
//   1. Build CSR (sorted-by-dst edge list) on device: hist -> scan -> fill.
//   2. Per layer: warp-per-node gather-mean (atomic-free), fused-K GEMM
//      ( [aggnorm | in] @ [Wl;Wr] + b ) with packed fma.rn.f32x2,
//      column stats reduction, BN finalize, apply.
//   3. Layer-1 BN apply fused with the final [128,2] linear -> d_out.
// ---------------------------------------------------------------------------

#define MAXN 50000
#define MAXE 1048576
#define TM 64   // GEMM rows per block

__device__ float g_agg [MAXN * 128];   // mean-aggregated (already / count)
__device__ float g_hpre[MAXN * 128];   // pre-BN GEMM output
__device__ float g_h0  [MAXN * 128];   // post BN+ReLU hidden
__device__ int   g_deg   [MAXN];
__device__ int   g_rowptr[MAXN + 1];
__device__ int   g_cursor[MAXN];
__device__ int   g_src   [MAXE];
__device__ int   g_dst   [MAXE];
__device__ int   g_ssort [MAXE];       // src sorted by dst
__device__ float g_stats [256];        // [0:128) col sums, [128:256) col sumsq
__device__ float g_scale [128];
__device__ float g_shift [128];
__device__ int   g_is64;

// ---------------- packed f32x2 helpers (sm_103a) ----------------
__device__ __forceinline__ unsigned long long pk2(float x, float y) {
    unsigned long long r;
    asm("mov.b64 %0, {%1, %2};" : "=l"(r) : "f"(x), "f"(y));
    return r;
}
__device__ __forceinline__ void upk2(unsigned long long v, float& x, float& y) {
    asm("mov.b64 {%0, %1}, %2;" : "=f"(x), "=f"(y) : "l"(v));
}
__device__ __forceinline__ void fma2(unsigned long long& d,
                                     unsigned long long a,
                                     unsigned long long b) {
    asm("fma.rn.f32x2 %0, %1, %2, %3;" : "=l"(d) : "l"(a), "l"(b), "l"(d));
}

// ---------------- edge preprocessing ----------------

// Detect int64 vs int32 edge_index: node ids < 50000, so int64 high words == 0.
__global__ void k_detect(const void* __restrict__ ei, int E) {
    if (blockIdx.x == 0 && threadIdx.x == 0) {
        const int* p = (const int*)ei;
        int m = E < 64 ? E : 64;
        int is64 = 1;
        for (int i = 0; i < m; i++) {
            if (p[2 * i + 1] != 0) { is64 = 0; break; }
        }
        g_is64 = is64;
    }
}

__global__ void k_convert(const void* __restrict__ ei, int E) {
    int i = blockIdx.x * blockDim.x + threadIdx.x;
    if (i >= E) return;
    if (g_is64) {
        const long long* q = (const long long*)ei;
        g_src[i] = (int)q[i];
        g_dst[i] = (int)q[E + i];
    } else {
        const int* q = (const int*)ei;
        g_src[i] = q[i];
        g_dst[i] = q[E + i];
    }
}

__global__ void k_zero_build(int n) {
    int i = blockIdx.x * blockDim.x + threadIdx.x;
    if (i < n) { g_deg[i] = 0; g_cursor[i] = 0; }
}

__global__ void k_hist(int E) {
    int i = blockIdx.x * blockDim.x + threadIdx.x;
    if (i < E) atomicAdd(&g_deg[g_dst[i]], 1);
}

// Single-block exclusive scan of degrees -> rowptr (shuffle-based).
__global__ void k_scan(int n) {
    __shared__ int warpsums[32];
    __shared__ int s_carry;
    int tid  = threadIdx.x;
    int lane = tid & 31;
    int wid  = tid >> 5;
    if (tid == 0) { g_rowptr[0] = 0; s_carry = 0; }
    __syncthreads();
    for (int base = 0; base < n; base += 1024) {
        int i = base + tid;
        int v = (i < n) ? g_deg[i] : 0;
        int x = v;
        #pragma unroll
        for (int off = 1; off < 32; off <<= 1) {
            int t = __shfl_up_sync(0xffffffffu, x, off);
            if (lane >= off) x += t;
        }
        if (lane == 31) warpsums[wid] = x;
        __syncthreads();
        if (wid == 0) {
            int w = warpsums[lane];
            #pragma unroll
            for (int off = 1; off < 32; off <<= 1) {
                int t = __shfl_up_sync(0xffffffffu, w, off);
                if (lane >= off) w += t;
            }
            warpsums[lane] = w;
        }
        __syncthreads();
        int wprefix = (wid > 0) ? warpsums[wid - 1] : 0;
        int incl = s_carry + wprefix + x;
        if (i < n) g_rowptr[i + 1] = incl;
        __syncthreads();              // all reads of s_carry done
        if (tid == 1023) s_carry = incl;
        __syncthreads();              // carry visible next tile
    }
}

__global__ void k_fill(int E) {
    int i = blockIdx.x * blockDim.x + threadIdx.x;
    if (i >= E) return;
    int d = g_dst[i];
    int p = g_rowptr[d] + atomicAdd(&g_cursor[d], 1);
    g_ssort[p] = g_src[i];
}

// ---------------- aggregation: warp per node, mean of x[src] ----------------
__global__ void k_aggregate(const float* __restrict__ xext, int use_h0, int n) {
    int gw   = (blockIdx.x * blockDim.x + threadIdx.x) >> 5;
    int lane = threadIdx.x & 31;
    if (gw >= n) return;
    const float* in = use_h0 ? g_h0 : xext;
    const float4* in4 = (const float4*)in;
    int e0 = g_rowptr[gw], e1 = g_rowptr[gw + 1];
    float4 acc = make_float4(0.f, 0.f, 0.f, 0.f);
    for (int e = e0; e < e1; e++) {
        int s = __ldg(&g_ssort[e]);
        float4 v = __ldg(&in4[s * 32 + lane]);
        acc.x += v.x; acc.y += v.y; acc.z += v.z; acc.w += v.w;
    }
    float inv = 1.0f / fmaxf((float)(e1 - e0), 1.0f);
    acc.x *= inv; acc.y *= inv; acc.z *= inv; acc.w *= inv;
    ((float4*)g_agg)[gw * 32 + lane] = acc;
}

// ---------------- GEMM: g_hpre = [g_agg | in] @ [Wl ; Wr] + b ----------------
// 256 threads: warp = 8-row group, lane = 4-col group. A tile in dynamic smem
// (broadcast LDS), W streamed float4 via L2, accumulators in packed f32x2.
__global__ void __launch_bounds__(256)
k_gemm(const float* __restrict__ xext, int use_h0,
       const float* __restrict__ Wl, const float* __restrict__ Wr,
       const float* __restrict__ bias, int n) {
    extern __shared__ float As[];   // [TM][256]
    const float* A1 = use_h0 ? g_h0 : xext;
    int tid  = threadIdx.x;
    int row0 = blockIdx.x * TM;

    const float4* A04 = (const float4*)g_agg;
    const float4* A14 = (const float4*)A1;
    float4* As4 = (float4*)As;
    for (int i = tid; i < TM * 64; i += 256) {
        int r = i >> 6, c = i & 63;
        int row = row0 + r;
        float4 v = make_float4(0.f, 0.f, 0.f, 0.f);
        if (row < n)
            v = (c < 32) ? __ldg(&A04[row * 32 + c]) : __ldg(&A14[row * 32 + (c - 32)]);
        As4[i] = v;
    }
    __syncthreads();

    int rg = tid >> 5;   // 0..7
    int cg = tid & 31;   // cols 4cg..4cg+3
    const float* Ab = As + rg * 8 * 256;

    float4 bv = __ldg(&((const float4*)bias)[cg]);
    unsigned long long b01 = pk2(bv.x, bv.y), b23 = pk2(bv.z, bv.w);
    unsigned long long acc[8][2];
    #pragma unroll
    for (int r = 0; r < 8; r++) { acc[r][0] = b01; acc[r][1] = b23; }

    const float4* Wl4 = (const float4*)Wl;
    const float4* Wr4 = (const float4*)Wr;

    #pragma unroll 4
    for (int k = 0; k < 128; k++) {
        float4 w = __ldg(&Wl4[k * 32 + cg]);
        unsigned long long w01 = pk2(w.x, w.y), w23 = pk2(w.z, w.w);
        #pragma unroll
        for (int r = 0; r < 8; r++) {
            float a = Ab[r * 256 + k];
            unsigned long long ap = pk2(a, a);
            fma2(acc[r][0], ap, w01);
            fma2(acc[r][1], ap, w23);
        }
    }
    #pragma unroll 4
    for (int k = 0; k < 128; k++) {
        float4 w = __ldg(&Wr4[k * 32 + cg]);
        unsigned long long w01 = pk2(w.x, w.y), w23 = pk2(w.z, w.w);
        #pragma unroll
        for (int r = 0; r < 8; r++) {
            float a = Ab[r * 256 + 128 + k];
            unsigned long long ap = pk2(a, a);
            fma2(acc[r][0], ap, w01);
            fma2(acc[r][1], ap, w23);
        }
    }

    float4* out4 = (float4*)g_hpre;
    #pragma unroll
    for (int r = 0; r < 8; r++) {
        int row = row0 + rg * 8 + r;
        if (row < n) {
            float4 v;
            upk2(acc[r][0], v.x, v.y);
            upk2(acc[r][1], v.z, v.w);
            out4[row * 32 + cg] = v;
        }
    }
}

// ---------------- BatchNorm stats ----------------
__global__ void k_zero_stats() {
    int i = threadIdx.x;
    if (i < 256) g_stats[i] = 0.f;
}

__global__ void k_colstats(int n) {
    int col = threadIdx.x;   // 128 threads
    float s = 0.f, sq = 0.f;
    for (int r = blockIdx.x; r < n; r += gridDim.x) {
        float v = g_hpre[r * 128 + col];
        s += v; sq += v * v;
    }
    atomicAdd(&g_stats[col], s);
    atomicAdd(&g_stats[128 + col], sq);
}

__global__ void k_finalize(const float* __restrict__ gamma,
                           const float* __restrict__ beta, int n) {
    int t = threadIdx.x;     // 128 threads
    float invn = 1.0f / (float)n;
    float mu  = g_stats[t] * invn;
    float var = g_stats[128 + t] * invn - mu * mu;
    var = fmaxf(var, 0.f);
    float rs = rsqrtf(var + 1e-5f);
    float sc = __ldg(&gamma[t]) * rs;
    g_scale[t] = sc;
    g_shift[t] = __ldg(&beta[t]) - mu * sc;
}

// ---------------- BN apply + ReLU -> g_h0 ----------------
__global__ void k_apply_relu(int n) {
    int n4 = n * 32;
    for (int i = blockIdx.x * blockDim.x + threadIdx.x; i < n4;
         i += gridDim.x * blockDim.x) {
        int cg = i & 31;
        float4 v  = ((const float4*)g_hpre)[i];
        float4 sc = ((const float4*)g_scale)[cg];
        float4 sh = ((const float4*)g_shift)[cg];
        v.x = fmaxf(v.x * sc.x + sh.x, 0.f);
        v.y = fmaxf(v.y * sc.y + sh.y, 0.f);
        v.z = fmaxf(v.z * sc.z + sh.z, 0.f);
        v.w = fmaxf(v.w * sc.w + sh.w, 0.f);
        ((float4*)g_h0)[i] = v;
    }
}

// ---------------- BN apply + ReLU + [128,2] linear -> d_out ----------------
__global__ void k_apply_out(const float* __restrict__ Wout,
                            const float* __restrict__ bout,
                            float* __restrict__ out, int n) {
    int gw   = (blockIdx.x * blockDim.x + threadIdx.x) >> 5;
    int lane = threadIdx.x & 31;
    if (gw >= n) return;
    float4 v  = ((const float4*)g_hpre)[gw * 32 + lane];
    float4 sc = ((const float4*)g_scale)[lane];
    float4 sh = ((const float4*)g_shift)[lane];
    v.x = fmaxf(v.x * sc.x + sh.x, 0.f);
    v.y = fmaxf(v.y * sc.y + sh.y, 0.f);
    v.z = fmaxf(v.z * sc.z + sh.z, 0.f);
    v.w = fmaxf(v.w * sc.w + sh.w, 0.f);
    // Wout row-major [128,2]; lane covers rows 4*lane..4*lane+3 -> 8 floats
    const float4* W4 = (const float4*)Wout;
    float4 wa = __ldg(&W4[lane * 2]);       // {W[j0][0],W[j0][1],W[j0+1][0],W[j0+1][1]}
    float4 wb = __ldg(&W4[lane * 2 + 1]);   // {W[j0+2][0],...}
    float s0 = v.x * wa.x + v.y * wa.z + v.z * wb.x + v.w * wb.z;
    float s1 = v.x * wa.y + v.y * wa.w + v.z * wb.y + v.w * wb.w;
    #pragma unroll
    for (int off = 16; off; off >>= 1) {
        s0 += __shfl_xor_sync(0xffffffffu, s0, off);
        s1 += __shfl_xor_sync(0xffffffffu, s1, off);
    }
    if (lane == 0) {
        out[gw * 2 + 0] = s0 + __ldg(&bout[0]);
        out[gw * 2 + 1] = s1 + __ldg(&bout[1]);
    }
}

// ---------------------------------------------------------------------------
extern "C" void kernel_launch(void* const* d_in, const int* in_sizes, int n_in,
                              void* d_out, int out_size) {
    const float* x    = (const float*)d_in[0];
    const void*  ei   = d_in[1];
    const float* Wl0  = (const float*)d_in[2];
    const float* Wr0  = (const float*)d_in[3];
    const float* b0   = (const float*)d_in[4];
    const float* gm0  = (const float*)d_in[5];
    const float* be0  = (const float*)d_in[6];
    const float* Wl1  = (const float*)d_in[7];
    const float* Wr1  = (const float*)d_in[8];
    const float* b1   = (const float*)d_in[9];
    const float* gm1  = (const float*)d_in[10];
    const float* be1  = (const float*)d_in[11];
    const float* Wout = (const float*)d_in[12];
    const float* bout = (const float*)d_in[13];
    float* out = (float*)d_out;

    int E = in_sizes[1] / 2;
    if (E > MAXE) E = MAXE;
    int n = out_size / 2;
    if (n > MAXN) n = MAXN;

    cudaFuncSetAttribute(k_gemm, cudaFuncAttributeMaxDynamicSharedMemorySize,
                         TM * 256 * (int)sizeof(float));

    int eb = (E + 255) / 256;
    int nb = (n + 255) / 256;
    int ab = (n * 32 + 255) / 256;          // warp-per-node launches
    int gb = (n + TM - 1) / TM;
    int smem = TM * 256 * (int)sizeof(float);

    // --- CSR build (shared by both layers) ---
    k_detect    <<<1, 32>>>(ei, E);
    k_zero_build<<<nb, 256>>>(n);
    k_convert   <<<eb, 256>>>(ei, E);
    k_hist      <<<eb, 256>>>(E);
    k_scan      <<<1, 1024>>>(n);
    k_fill      <<<eb, 256>>>(E);

    // --- layer 0 ---
    k_aggregate <<<ab, 256>>>(x, 0, n);
    k_gemm      <<<gb, 256, smem>>>(x, 0, Wl0, Wr0, b0, n);
    k_zero_stats<<<1, 256>>>();
    k_colstats  <<<256, 128>>>(n);
    k_finalize  <<<1, 128>>>(gm0, be0, n);
    k_apply_relu<<<2048, 256>>>(n);

    // --- layer 1 ---
    k_aggregate <<<ab, 256>>>(nullptr, 1, n);
    k_gemm      <<<gb, 256, smem>>>(nullptr, 1, Wl1, Wr1, b1, n);
    k_zero_stats<<<1, 256>>>();
    k_colstats  <<<256, 128>>>(n);
    k_finalize  <<<1, 128>>>(gm1, be1, n);

    // --- fused BN+ReLU+Linear[128->2] -> d_out ---
    k_apply_out <<<ab, 256>>>(Wout, bout, out, n);
}

// round 7
// speedup vs baseline: 1.4561x; 1.4561x over previous
#include <cuda_runtime.h>
#include <cuda_bf16.h>
#include <cstdint>

// ---------------------------------------------------------------------------
// GraphSAGE: 2x (SAGEConv -> BN(train) -> ReLU) -> Linear[128->2]
//  - CSR build on device (hist -> 8-wide scan -> fill)
//  - warp-per-node gather-mean, emits bf16 hi/lo split directly
//  - GEMM  [agg | in] @ [Wl;Wr] + b  via mma.sync m16n8k16 bf16 (split x3)
//  - BN stats / finalize; layer-1 BN+ReLU fused with final [128,2] linear
// ---------------------------------------------------------------------------

#define MAXN 50000
#define MAXE 1048576

__device__ float g_hpre[MAXN * 128];
__device__ float g_h0  [MAXN * 128];
__device__ __nv_bfloat16 g_aggh[MAXN * 128];
__device__ __nv_bfloat16 g_aggl[MAXN * 128];
__device__ __nv_bfloat16 g_xh  [MAXN * 128];
__device__ __nv_bfloat16 g_xl  [MAXN * 128];
__device__ __nv_bfloat16 g_h0h [MAXN * 128];
__device__ __nv_bfloat16 g_h0l [MAXN * 128];
__device__ __nv_bfloat16 g_wth [2][128 * 256];   // [layer][n][k] transposed hi
__device__ __nv_bfloat16 g_wtl [2][128 * 256];   // lo
__device__ int   g_deg   [MAXN];
__device__ int   g_rowptr[MAXN + 1];
__device__ int   g_cursor[MAXN];
__device__ int   g_src   [MAXE];
__device__ int   g_dst   [MAXE];
__device__ int   g_ssort [MAXE];
__device__ float g_stats [256];
__device__ float g_scale [128];
__device__ float g_shift [128];
__device__ int   g_is64;

// ---------------- PTX helpers ----------------
__device__ __forceinline__ uint32_t s2u(const void* p) {
    uint32_t a;
    asm("{ .reg .u64 t; cvta.to.shared.u64 t, %1; cvt.u32.u64 %0, t; }"
        : "=r"(a) : "l"(p));
    return a;
}

__device__ __forceinline__ void ldm4(uint32_t* r, uint32_t addr) {
    asm volatile("ldmatrix.sync.aligned.m8n8.x4.shared.b16 {%0,%1,%2,%3}, [%4];"
        : "=r"(r[0]), "=r"(r[1]), "=r"(r[2]), "=r"(r[3]) : "r"(addr));
}

__device__ __forceinline__ void mma16816(float* d, const uint32_t* a,
                                         uint32_t b0, uint32_t b1) {
    asm volatile(
        "mma.sync.aligned.m16n8k16.row.col.f32.bf16.bf16.f32 "
        "{%0,%1,%2,%3}, {%4,%5,%6,%7}, {%8,%9}, {%0,%1,%2,%3};"
        : "+f"(d[0]), "+f"(d[1]), "+f"(d[2]), "+f"(d[3])
        : "r"(a[0]), "r"(a[1]), "r"(a[2]), "r"(a[3]), "r"(b0), "r"(b1));
}

// smem layout for GEMM (bytes)
#define SM_A  0            // A: 2 halves x 4 k-sections x [128r][64c bf16] = 131072
#define SM_W  131072       // W chunk: 2 halves x 2 k-sections x [128n][64k] = 65536
#define SM_TOTAL 196608

// ---------------- edge preprocessing ----------------
__global__ void k_detect(const void* __restrict__ ei, int E) {
    if (threadIdx.x == 0) {
        const int* p = (const int*)ei;
        int m = E < 64 ? E : 64, is64 = 1;
        for (int i = 0; i < m; i++)
            if (p[2 * i + 1] != 0) { is64 = 0; break; }
        g_is64 = is64;
    }
}

__global__ void k_zero_build(int n) {
    int i = blockIdx.x * blockDim.x + threadIdx.x;
    if (i < n) { g_deg[i] = 0; g_cursor[i] = 0; }
}

__global__ void k_edges(const void* __restrict__ ei, int E) {
    int i = blockIdx.x * blockDim.x + threadIdx.x;
    if (i >= E) return;
    int s, d;
    if (g_is64) {
        const long long* q = (const long long*)ei;
        s = (int)q[i]; d = (int)q[E + i];
    } else {
        const int* q = (const int*)ei;
        s = q[i]; d = q[E + i];
    }
    g_src[i] = s; g_dst[i] = d;
    atomicAdd(&g_deg[d], 1);
}

// single-block scan, 8 elems/thread
__global__ void k_scan(int n) {
    __shared__ int warpsums[32];
    __shared__ int s_carry;
    int tid = threadIdx.x, lane = tid & 31, wid = tid >> 5;
    if (tid == 0) { g_rowptr[0] = 0; s_carry = 0; }
    __syncthreads();
    for (int base = 0; base < n; base += 8192) {
        int i0 = base + tid * 8;
        int v[8], tot = 0;
        #pragma unroll
        for (int j = 0; j < 8; j++) {
            int i = i0 + j;
            v[j] = (i < n) ? g_deg[i] : 0;
            tot += v[j];
        }
        int x = tot;
        #pragma unroll
        for (int off = 1; off < 32; off <<= 1) {
            int t = __shfl_up_sync(0xffffffffu, x, off);
            if (lane >= off) x += t;
        }
        if (lane == 31) warpsums[wid] = x;
        __syncthreads();
        if (wid == 0) {
            int w = warpsums[lane];
            #pragma unroll
            for (int off = 1; off < 32; off <<= 1) {
                int t = __shfl_up_sync(0xffffffffu, w, off);
                if (lane >= off) w += t;
            }
            warpsums[lane] = w;
        }
        __syncthreads();
        int wprefix = (wid > 0) ? warpsums[wid - 1] : 0;
        int run = s_carry + wprefix + (x - tot);
        int newcarry = run + tot;
        #pragma unroll
        for (int j = 0; j < 8; j++) {
            run += v[j];
            if (i0 + j < n) g_rowptr[i0 + j + 1] = run;
        }
        __syncthreads();
        if (tid == 1023) s_carry = newcarry;
        __syncthreads();
    }
}

__global__ void k_fill(int E) {
    int i = blockIdx.x * blockDim.x + threadIdx.x;
    if (i >= E) return;
    int d = g_dst[i];
    int p = g_rowptr[d] + atomicAdd(&g_cursor[d], 1);
    g_ssort[p] = g_src[i];
}

// ---------------- fp32 -> bf16 hi/lo split helpers ----------------
__device__ __forceinline__ void split4(float4 v,
        __nv_bfloat16* ph, __nv_bfloat16* pl) {
    __nv_bfloat16 hx = __float2bfloat16(v.x), hy = __float2bfloat16(v.y);
    __nv_bfloat16 hz = __float2bfloat16(v.z), hw = __float2bfloat16(v.w);
    __nv_bfloat162* h2 = (__nv_bfloat162*)ph;
    h2[0] = __halves2bfloat162(hx, hy);
    h2[1] = __halves2bfloat162(hz, hw);
    __nv_bfloat162* l2 = (__nv_bfloat162*)pl;
    l2[0] = __halves2bfloat162(__float2bfloat16(v.x - __bfloat162float(hx)),
                               __float2bfloat16(v.y - __bfloat162float(hy)));
    l2[1] = __halves2bfloat162(__float2bfloat16(v.z - __bfloat162float(hz)),
                               __float2bfloat16(v.w - __bfloat162float(hw)));
}

__global__ void k_split_x(const float* __restrict__ x, int n) {
    int i = blockIdx.x * blockDim.x + threadIdx.x;   // over n*32 float4 groups
    if (i >= n * 32) return;
    float4 v = __ldg(&((const float4*)x)[i]);
    split4(v, g_xh + (size_t)i * 4, g_xl + (size_t)i * 4);
}

__global__ void k_prep_w(const float* __restrict__ Wl,
                         const float* __restrict__ Wr, int layer) {
    int i = blockIdx.x * blockDim.x + threadIdx.x;   // 128*256
    if (i >= 128 * 256) return;
    int nn = i >> 8, k = i & 255;
    float v = (k < 128) ? __ldg(&Wl[k * 128 + nn]) : __ldg(&Wr[(k - 128) * 128 + nn]);
    __nv_bfloat16 h = __float2bfloat16(v);
    g_wth[layer][i] = h;
    g_wtl[layer][i] = __float2bfloat16(v - __bfloat162float(h));
}

// ---------------- aggregation: warp per node, mean -> bf16 hi/lo ----------------
__global__ void k_aggregate(const float* __restrict__ xext, int use_h0, int n) {
    int gw   = (blockIdx.x * blockDim.x + threadIdx.x) >> 5;
    int lane = threadIdx.x & 31;
    if (gw >= n) return;
    const float4* in4 = (const float4*)(use_h0 ? g_h0 : xext);
    int e0 = g_rowptr[gw], e1 = g_rowptr[gw + 1];
    float4 acc = make_float4(0.f, 0.f, 0.f, 0.f);
    for (int e = e0; e < e1; e++) {
        int s = __ldg(&g_ssort[e]);
        float4 v = __ldg(&in4[s * 32 + lane]);
        acc.x += v.x; acc.y += v.y; acc.z += v.z; acc.w += v.w;
    }
    float inv = 1.0f / fmaxf((float)(e1 - e0), 1.0f);
    acc.x *= inv; acc.y *= inv; acc.z *= inv; acc.w *= inv;
    size_t off = (size_t)gw * 128 + lane * 4;
    split4(acc, g_aggh + off, g_aggl + off);
}

// ---------------- mma.sync GEMM: g_hpre = [agg | in] @ Wt^T + b ----------------
// Block tile: 128 rows x 128 cols, K=256 in 2 W-chunks of 128.
// A (hi+lo, full K) resident in smem; products hi*hi + hi*lo + lo*hi.
// smem layout: 128-byte rows of 64 bf16, SW128 xor swizzle (granule ^= row%8).
__global__ void __launch_bounds__(256, 1)
k_gemm_mma(int layer, int use_x, const float* __restrict__ bias, int n) {
    extern __shared__ char smem[];
    uint32_t sb = s2u(smem);
    int tid  = threadIdx.x;
    int wid  = tid >> 5;
    int lane = tid & 31;
    int row0 = blockIdx.x * 128;

    const __nv_bfloat16* inh = use_x ? g_xh : g_h0h;
    const __nv_bfloat16* inl = use_x ? g_xl : g_h0l;

    // ---- load A tile (hi + lo), 8192 uint4 ----
    for (int i = tid; i < 8192; i += 256) {
        int half = i >> 12;
        int j = i & 4095;
        int r  = j >> 5;                 // 0..127
        int g8 = j & 31;                 // granule across 256 cols
        int c0 = g8 * 8;
        int s  = c0 >> 6;
        int gin = (c0 >> 3) & 7;
        int row = row0 + r;
        uint4 v = make_uint4(0, 0, 0, 0);
        const __nv_bfloat16* base =
            half ? ((c0 < 128) ? g_aggl : inl) : ((c0 < 128) ? g_aggh : inh);
        int cc = (c0 < 128) ? c0 : c0 - 128;
        if (row < n)
            v = __ldg((const uint4*)(base + (size_t)row * 128 + cc));
        *(uint4*)(smem + SM_A + half * 65536 + s * 16384 + r * 128 +
                  ((gin ^ (r & 7)) * 16)) = v;
    }

    int wm = wid >> 1, wn = wid & 1;
    int m0 = wm * 32, n0 = wn * 64;
    float acc[2][8][4];
    #pragma unroll
    for (int mf = 0; mf < 2; mf++)
        #pragma unroll
        for (int nf = 0; nf < 8; nf++)
            #pragma unroll
            for (int q = 0; q < 4; q++) acc[mf][nf][q] = 0.f;

    // per-thread ldmatrix addressing constants
    int lx    = lane & 7;                       // swizzle xor
    int aRow  = lane & 15;                      // +16*mf
    int aKoff = lane >> 4;                      // granule +0/1
    int wRow  = (lane & 7) + ((lane >> 4) << 3);
    int wKoff = (lane >> 3) & 1;

    const __nv_bfloat16* wth = g_wth[layer];
    const __nv_bfloat16* wtl = g_wtl[layer];

    #pragma unroll 1
    for (int kc = 0; kc < 2; kc++) {
        __syncthreads();   // A ready (kc=0) / prev compute done (kc=1)
        // ---- load W chunk (hi + lo), 4096 uint4 ----
        for (int i = tid; i < 4096; i += 256) {
            int half = i >> 11;
            int j = i & 2047;
            int r  = j >> 4;             // n row
            int kin = (j & 15) * 8;
            int s2 = kin >> 6;
            int gin = (kin >> 3) & 7;
            const __nv_bfloat16* base = half ? wtl : wth;
            uint4 v = __ldg((const uint4*)(base + (size_t)r * 256 + kc * 128 + kin));
            *(uint4*)(smem + SM_W + half * 32768 + s2 * 16384 + r * 128 +
                      ((gin ^ (r & 7)) * 16)) = v;
        }
        __syncthreads();

        #pragma unroll 1
        for (int ksl = 0; ksl < 8; ksl++) {
            int ks   = kc * 8 + ksl;
            int sA   = ks >> 2;
            int kgA  = (ks & 3) * 2 + aKoff;        // granule in 64-col section
            int s2   = ksl >> 2;
            int kgW  = (ksl & 3) * 2 + wKoff;

            #pragma unroll
            for (int ah = 0; ah < 2; ah++) {
                uint32_t af[2][4];
                #pragma unroll
                for (int mf = 0; mf < 2; mf++) {
                    int r = m0 + mf * 16 + aRow;
                    uint32_t addr = sb + SM_A + ah * 65536 + sA * 16384 +
                                    r * 128 + ((kgA ^ lx) * 16);
                    ldm4(af[mf], addr);
                }
                int nwh = (ah == 0) ? 2 : 1;        // Ah*{Wh,Wl}, Al*Wh
                #pragma unroll
                for (int wh = 0; wh < 2; wh++) {
                    if (wh >= nwh) break;
                    #pragma unroll
                    for (int np = 0; np < 4; np++) {
                        uint32_t wf[4];
                        int r = n0 + np * 16 + wRow;
                        uint32_t addr = sb + SM_W + wh * 32768 + s2 * 16384 +
                                        r * 128 + ((kgW ^ lx) * 16);
                        ldm4(wf, addr);
                        #pragma unroll
                        for (int mf = 0; mf < 2; mf++) {
                            mma16816(acc[mf][np * 2],     af[mf], wf[0], wf[1]);
                            mma16816(acc[mf][np * 2 + 1], af[mf], wf[2], wf[3]);
                        }
                    }
                }
            }
        }
    }

    // ---- epilogue: add bias, store fp32 ----
    #pragma unroll
    for (int mf = 0; mf < 2; mf++) {
        int row = row0 + m0 + mf * 16 + (lane >> 2);
        #pragma unroll
        for (int nf = 0; nf < 8; nf++) {
            int col = n0 + nf * 8 + (lane & 3) * 2;
            float bx = __ldg(&bias[col]), by = __ldg(&bias[col + 1]);
            if (row < n) {
                float2 o = make_float2(acc[mf][nf][0] + bx, acc[mf][nf][1] + by);
                *(float2*)(g_hpre + (size_t)row * 128 + col) = o;
            }
            if (row + 8 < n) {
                float2 o = make_float2(acc[mf][nf][2] + bx, acc[mf][nf][3] + by);
                *(float2*)(g_hpre + (size_t)(row + 8) * 128 + col) = o;
            }
        }
    }
}

// ---------------- BatchNorm ----------------
__global__ void k_zero_stats() {
    if (threadIdx.x < 256) g_stats[threadIdx.x] = 0.f;
}

__global__ void k_colstats(int n) {
    int col = threadIdx.x;
    float s = 0.f, sq = 0.f;
    for (int r = blockIdx.x; r < n; r += gridDim.x) {
        float v = g_hpre[(size_t)r * 128 + col];
        s += v; sq += v * v;
    }
    atomicAdd(&g_stats[col], s);
    atomicAdd(&g_stats[128 + col], sq);
}

__global__ void k_finalize(const float* __restrict__ gamma,
                           const float* __restrict__ beta, int n) {
    int t = threadIdx.x;
    float invn = 1.0f / (float)n;
    float mu  = g_stats[t] * invn;
    float var = fmaxf(g_stats[128 + t] * invn - mu * mu, 0.f);
    float rs = rsqrtf(var + 1e-5f);
    float sc = __ldg(&gamma[t]) * rs;
    g_scale[t] = sc;
    g_shift[t] = __ldg(&beta[t]) - mu * sc;
}

// BN apply + ReLU -> g_h0 (fp32) + bf16 hi/lo
__global__ void k_apply_relu(int n) {
    int n4 = n * 32;
    for (int i = blockIdx.x * blockDim.x + threadIdx.x; i < n4;
         i += gridDim.x * blockDim.x) {
        int cg = i & 31;
        float4 v  = ((const float4*)g_hpre)[i];
        float4 sc = ((const float4*)g_scale)[cg];
        float4 sh = ((const float4*)g_shift)[cg];
        v.x = fmaxf(v.x * sc.x + sh.x, 0.f);
        v.y = fmaxf(v.y * sc.y + sh.y, 0.f);
        v.z = fmaxf(v.z * sc.z + sh.z, 0.f);
        v.w = fmaxf(v.w * sc.w + sh.w, 0.f);
        ((float4*)g_h0)[i] = v;
        split4(v, g_h0h + (size_t)i * 4, g_h0l + (size_t)i * 4);
    }
}

// BN apply + ReLU + [128,2] linear -> d_out
__global__ void k_apply_out(const float* __restrict__ Wout,
                            const float* __restrict__ bout,
                            float* __restrict__ out, int n) {
    int gw   = (blockIdx.x * blockDim.x + threadIdx.x) >> 5;
    int lane = threadIdx.x & 31;
    if (gw >= n) return;
    float4 v  = ((const float4*)g_hpre)[gw * 32 + lane];
    float4 sc = ((const float4*)g_scale)[lane];
    float4 sh = ((const float4*)g_shift)[lane];
    v.x = fmaxf(v.x * sc.x + sh.x, 0.f);
    v.y = fmaxf(v.y * sc.y + sh.y, 0.f);
    v.z = fmaxf(v.z * sc.z + sh.z, 0.f);
    v.w = fmaxf(v.w * sc.w + sh.w, 0.f);
    const float4* W4 = (const float4*)Wout;
    float4 wa = __ldg(&W4[lane * 2]);
    float4 wb = __ldg(&W4[lane * 2 + 1]);
    float s0 = v.x * wa.x + v.y * wa.z + v.z * wb.x + v.w * wb.z;
    float s1 = v.x * wa.y + v.y * wa.w + v.z * wb.y + v.w * wb.w;
    #pragma unroll
    for (int off = 16; off; off >>= 1) {
        s0 += __shfl_xor_sync(0xffffffffu, s0, off);
        s1 += __shfl_xor_sync(0xffffffffu, s1, off);
    }
    if (lane == 0) {
        out[gw * 2 + 0] = s0 + __ldg(&bout[0]);
        out[gw * 2 + 1] = s1 + __ldg(&bout[1]);
    }
}

// ---------------------------------------------------------------------------
extern "C" void kernel_launch(void* const* d_in, const int* in_sizes, int n_in,
                              void* d_out, int out_size) {
    const float* x    = (const float*)d_in[0];
    const void*  ei   = d_in[1];
    const float* Wl0  = (const float*)d_in[2];
    const float* Wr0  = (const float*)d_in[3];
    const float* b0   = (const float*)d_in[4];
    const float* gm0  = (const float*)d_in[5];
    const float* be0  = (const float*)d_in[6];
    const float* Wl1  = (const float*)d_in[7];
    const float* Wr1  = (const float*)d_in[8];
    const float* b1   = (const float*)d_in[9];
    const float* gm1  = (const float*)d_in[10];
    const float* be1  = (const float*)d_in[11];
    const float* Wout = (const float*)d_in[12];
    const float* bout = (const float*)d_in[13];
    float* out = (float*)d_out;

    int E = in_sizes[1] / 2;  if (E > MAXE) E = MAXE;
    int n = out_size / 2;     if (n > MAXN) n = MAXN;

    cudaFuncSetAttribute(k_gemm_mma,
        cudaFuncAttributeMaxDynamicSharedMemorySize, SM_TOTAL);

    int eb = (E + 255) / 256;
    int nb = (n + 255) / 256;
    int ab = (n * 32 + 255) / 256;          // warp-per-node / float4-per-thread
    int gb = (n + 127) / 128;

    // --- CSR build + splits ---
    k_detect    <<<1, 32>>>(ei, E);
    k_zero_build<<<nb, 256>>>(n);
    k_edges     <<<eb, 256>>>(ei, E);
    k_scan      <<<1, 1024>>>(n);
    k_fill      <<<eb, 256>>>(E);
    k_split_x   <<<ab, 256>>>(x, n);
    k_prep_w    <<<128, 256>>>(Wl0, Wr0, 0);
    k_prep_w    <<<128, 256>>>(Wl1, Wr1, 1);

    // --- layer 0 ---
    k_aggregate <<<ab, 256>>>(x, 0, n);
    k_gemm_mma  <<<gb, 256, SM_TOTAL>>>(0, 1, b0, n);
    k_zero_stats<<<1, 256>>>();
    k_colstats  <<<256, 128>>>(n);
    k_finalize  <<<1, 128>>>(gm0, be0, n);
    k_apply_relu<<<2048, 256>>>(n);

    // --- layer 1 ---
    k_aggregate <<<ab, 256>>>(nullptr, 1, n);
    k_gemm_mma  <<<gb, 256, SM_TOTAL>>>(1, 0, b1, n);
    k_zero_stats<<<1, 256>>>();
    k_colstats  <<<256, 128>>>(n);
    k_finalize  <<<1, 128>>>(gm1, be1, n);

    // --- fused BN+ReLU+Linear[128->2] -> d_out ---
    k_apply_out <<<ab, 256>>>(Wout, bout, out, n);
}

// round 8
// speedup vs baseline: 1.9344x; 1.3285x over previous
#include <cuda_runtime.h>
#include <cuda_bf16.h>
#include <cstdint>

// ---------------------------------------------------------------------------
// GraphSAGE: 2x (SAGEConv -> BN(train) -> ReLU) -> Linear[128->2]
//  - CSR build on device (hist -> multi-block scan -> fill)
//  - warp-per-node gather-mean, emits bf16 hi/lo split directly
//  - GEMM  [agg | in] @ [Wl;Wr] + b  via mma.sync m16n8k16 bf16 (split x3),
//    BN column stats fused into the GEMM epilogue (atomicAdd)
//  - BN finalize; layer-1 BN+ReLU fused with final [128,2] linear
// ---------------------------------------------------------------------------

#define MAXN 50000
#define MAXE 1048576

__device__ float g_hpre[MAXN * 128];
__device__ float g_h0  [MAXN * 128];
__device__ __nv_bfloat16 g_aggh[MAXN * 128];
__device__ __nv_bfloat16 g_aggl[MAXN * 128];
__device__ __nv_bfloat16 g_xh  [MAXN * 128];
__device__ __nv_bfloat16 g_xl  [MAXN * 128];
__device__ __nv_bfloat16 g_h0h [MAXN * 128];
__device__ __nv_bfloat16 g_h0l [MAXN * 128];
__device__ __nv_bfloat16 g_wth [2][128 * 256];   // [layer][n][k] transposed hi
__device__ __nv_bfloat16 g_wtl [2][128 * 256];   // lo
__device__ int   g_deg   [MAXN];
__device__ int   g_rowptr[MAXN + 1];
__device__ int   g_cursor[MAXN];
__device__ int   g_src   [MAXE];
__device__ int   g_dst   [MAXE];
__device__ int   g_ssort [MAXE];
__device__ int   g_bsum  [64];
__device__ int   g_boff  [64];
__device__ float g_stats [256];
__device__ float g_scale [128];
__device__ float g_shift [128];
__device__ int   g_is64;

// ---------------- PTX helpers ----------------
__device__ __forceinline__ uint32_t s2u(const void* p) {
    uint32_t a;
    asm("{ .reg .u64 t; cvta.to.shared.u64 t, %1; cvt.u32.u64 %0, t; }"
        : "=r"(a) : "l"(p));
    return a;
}

__device__ __forceinline__ void ldm4(uint32_t* r, uint32_t addr) {
    asm volatile("ldmatrix.sync.aligned.m8n8.x4.shared.b16 {%0,%1,%2,%3}, [%4];"
        : "=r"(r[0]), "=r"(r[1]), "=r"(r[2]), "=r"(r[3]) : "r"(addr));
}

__device__ __forceinline__ void mma16816(float* d, const uint32_t* a,
                                         uint32_t b0, uint32_t b1) {
    asm volatile(
        "mma.sync.aligned.m16n8k16.row.col.f32.bf16.bf16.f32 "
        "{%0,%1,%2,%3}, {%4,%5,%6,%7}, {%8,%9}, {%0,%1,%2,%3};"
        : "+f"(d[0]), "+f"(d[1]), "+f"(d[2]), "+f"(d[3])
        : "r"(a[0]), "r"(a[1]), "r"(a[2]), "r"(a[3]), "r"(b0), "r"(b1));
}

// smem layout for GEMM (bytes)
#define SM_A  0            // A: 2 halves x 4 k-sections x [128r][64c bf16] = 131072
#define SM_W  131072       // W chunk: 2 halves x 2 k-sections x [128n][64k] = 65536
#define SM_TOTAL 196608

// ---------------- edge preprocessing ----------------
__global__ void k_detect(const void* __restrict__ ei, int E) {
    if (threadIdx.x == 0) {
        const int* p = (const int*)ei;
        int m = E < 64 ? E : 64, is64 = 1;
        for (int i = 0; i < m; i++)
            if (p[2 * i + 1] != 0) { is64 = 0; break; }
        g_is64 = is64;
    }
}

__global__ void k_zero_build(int n) {
    int i = blockIdx.x * blockDim.x + threadIdx.x;
    if (i < n) { g_deg[i] = 0; g_cursor[i] = 0; }
    if (i < 256) g_stats[i] = 0.f;
}

__global__ void k_edges(const void* __restrict__ ei, int E) {
    int i = blockIdx.x * blockDim.x + threadIdx.x;
    if (i >= E) return;
    int s, d;
    if (g_is64) {
        const long long* q = (const long long*)ei;
        s = (int)q[i]; d = (int)q[E + i];
    } else {
        const int* q = (const int*)ei;
        s = q[i]; d = q[E + i];
    }
    g_src[i] = s; g_dst[i] = d;
    atomicAdd(&g_deg[d], 1);
}

// ---------------- multi-block scan: deg -> rowptr ----------------
// pass 1: per-block (2048 elems) inclusive scan, block total to g_bsum
__global__ void k_scan1(int n) {
    __shared__ int warpsums[8];
    int tid = threadIdx.x, lane = tid & 31, wid = tid >> 5;
    int i0 = blockIdx.x * 2048 + tid * 8;
    int v[8], tot = 0;
    #pragma unroll
    for (int j = 0; j < 8; j++) {
        v[j] = (i0 + j < n) ? g_deg[i0 + j] : 0;
        tot += v[j];
    }
    int x = tot;
    #pragma unroll
    for (int off = 1; off < 32; off <<= 1) {
        int t = __shfl_up_sync(0xffffffffu, x, off);
        if (lane >= off) x += t;
    }
    if (lane == 31) warpsums[wid] = x;
    __syncthreads();
    if (wid == 0) {
        int w = (lane < 8) ? warpsums[lane] : 0;
        #pragma unroll
        for (int off = 1; off < 8; off <<= 1) {
            int t = __shfl_up_sync(0xffffffffu, w, off);
            if (lane >= off) w += t;
        }
        if (lane < 8) warpsums[lane] = w;
    }
    __syncthreads();
    int wpref = (wid > 0) ? warpsums[wid - 1] : 0;
    int run = wpref + (x - tot);
    #pragma unroll
    for (int j = 0; j < 8; j++) {
        run += v[j];
        if (i0 + j < n) g_rowptr[i0 + j + 1] = run;
    }
    if (tid == 0) g_bsum[blockIdx.x] = warpsums[7];
}

// pass 2: exclusive scan of <=64 block sums (1 warp, 2 elems/lane)
__global__ void k_scan2(int nb) {
    int lane = threadIdx.x;
    int a = (2 * lane     < nb) ? g_bsum[2 * lane]     : 0;
    int b = (2 * lane + 1 < nb) ? g_bsum[2 * lane + 1] : 0;
    int t = a + b;
    int x = t;
    #pragma unroll
    for (int off = 1; off < 32; off <<= 1) {
        int u = __shfl_up_sync(0xffffffffu, x, off);
        if (lane >= off) x += u;
    }
    int excl = x - t;
    if (2 * lane     < nb) g_boff[2 * lane]     = excl;
    if (2 * lane + 1 < nb) g_boff[2 * lane + 1] = excl + a;
}

// pass 3: add block offsets
__global__ void k_scan3(int n) {
    int i = blockIdx.x * blockDim.x + threadIdx.x;
    if (i == 0) g_rowptr[0] = 0;
    if (i < n) g_rowptr[i + 1] += g_boff[i >> 11];
}

__global__ void k_fill(int E) {
    int i = blockIdx.x * blockDim.x + threadIdx.x;
    if (i >= E) return;
    int d = g_dst[i];
    int p = g_rowptr[d] + atomicAdd(&g_cursor[d], 1);
    g_ssort[p] = g_src[i];
}

// ---------------- fp32 -> bf16 hi/lo split helpers ----------------
__device__ __forceinline__ void split4(float4 v,
        __nv_bfloat16* ph, __nv_bfloat16* pl) {
    __nv_bfloat16 hx = __float2bfloat16(v.x), hy = __float2bfloat16(v.y);
    __nv_bfloat16 hz = __float2bfloat16(v.z), hw = __float2bfloat16(v.w);
    __nv_bfloat162* h2 = (__nv_bfloat162*)ph;
    h2[0] = __halves2bfloat162(hx, hy);
    h2[1] = __halves2bfloat162(hz, hw);
    __nv_bfloat162* l2 = (__nv_bfloat162*)pl;
    l2[0] = __halves2bfloat162(__float2bfloat16(v.x - __bfloat162float(hx)),
                               __float2bfloat16(v.y - __bfloat162float(hy)));
    l2[1] = __halves2bfloat162(__float2bfloat16(v.z - __bfloat162float(hz)),
                               __float2bfloat16(v.w - __bfloat162float(hw)));
}

__global__ void k_split_x(const float* __restrict__ x, int n) {
    int i = blockIdx.x * blockDim.x + threadIdx.x;   // over n*32 float4 groups
    if (i >= n * 32) return;
    float4 v = __ldg(&((const float4*)x)[i]);
    split4(v, g_xh + (size_t)i * 4, g_xl + (size_t)i * 4);
}

__global__ void k_prep_w(const float* __restrict__ Wl,
                         const float* __restrict__ Wr, int layer) {
    int i = blockIdx.x * blockDim.x + threadIdx.x;   // 128*256
    if (i >= 128 * 256) return;
    int nn = i >> 8, k = i & 255;
    float v = (k < 128) ? __ldg(&Wl[k * 128 + nn]) : __ldg(&Wr[(k - 128) * 128 + nn]);
    __nv_bfloat16 h = __float2bfloat16(v);
    g_wth[layer][i] = h;
    g_wtl[layer][i] = __float2bfloat16(v - __bfloat162float(h));
}

// ---------------- aggregation: warp per node, mean -> bf16 hi/lo ----------------
__global__ void k_aggregate(const float* __restrict__ xext, int use_h0, int n) {
    int gw   = (blockIdx.x * blockDim.x + threadIdx.x) >> 5;
    int lane = threadIdx.x & 31;
    if (gw >= n) return;
    const float4* in4 = (const float4*)(use_h0 ? g_h0 : xext);
    int e0 = g_rowptr[gw], e1 = g_rowptr[gw + 1];
    float4 acc = make_float4(0.f, 0.f, 0.f, 0.f);
    for (int e = e0; e < e1; e++) {
        int s = __ldg(&g_ssort[e]);
        float4 v = __ldg(&in4[s * 32 + lane]);
        acc.x += v.x; acc.y += v.y; acc.z += v.z; acc.w += v.w;
    }
    float inv = 1.0f / fmaxf((float)(e1 - e0), 1.0f);
    acc.x *= inv; acc.y *= inv; acc.z *= inv; acc.w *= inv;
    size_t off = (size_t)gw * 128 + lane * 4;
    split4(acc, g_aggh + off, g_aggl + off);
}

// ---------------- mma.sync GEMM + fused BN column stats ----------------
// Block tile: 128 rows x 128 cols, K=256 in 2 W-chunks of 128.
// A (hi+lo, full K) resident in smem; products hi*hi + hi*lo + lo*hi.
// Epilogue: add bias, store fp32, and atomicAdd column sum/sumsq to g_stats.
__global__ void __launch_bounds__(256, 1)
k_gemm_mma(int layer, int use_x, const float* __restrict__ bias, int n) {
    extern __shared__ char smem[];
    uint32_t sb = s2u(smem);
    int tid  = threadIdx.x;
    int wid  = tid >> 5;
    int lane = tid & 31;
    int row0 = blockIdx.x * 128;

    const __nv_bfloat16* inh = use_x ? g_xh : g_h0h;
    const __nv_bfloat16* inl = use_x ? g_xl : g_h0l;

    // ---- load A tile (hi + lo), 8192 uint4 ----
    for (int i = tid; i < 8192; i += 256) {
        int half = i >> 12;
        int j = i & 4095;
        int r  = j >> 5;                 // 0..127
        int g8 = j & 31;                 // granule across 256 cols
        int c0 = g8 * 8;
        int s  = c0 >> 6;
        int gin = (c0 >> 3) & 7;
        int row = row0 + r;
        uint4 v = make_uint4(0, 0, 0, 0);
        const __nv_bfloat16* base =
            half ? ((c0 < 128) ? g_aggl : inl) : ((c0 < 128) ? g_aggh : inh);
        int cc = (c0 < 128) ? c0 : c0 - 128;
        if (row < n)
            v = __ldg((const uint4*)(base + (size_t)row * 128 + cc));
        *(uint4*)(smem + SM_A + half * 65536 + s * 16384 + r * 128 +
                  ((gin ^ (r & 7)) * 16)) = v;
    }

    int wm = wid >> 1, wn = wid & 1;
    int m0 = wm * 32, n0 = wn * 64;
    float acc[2][8][4];
    #pragma unroll
    for (int mf = 0; mf < 2; mf++)
        #pragma unroll
        for (int nf = 0; nf < 8; nf++)
            #pragma unroll
            for (int q = 0; q < 4; q++) acc[mf][nf][q] = 0.f;

    // per-thread ldmatrix addressing constants
    int lx    = lane & 7;                       // swizzle xor
    int aRow  = lane & 15;                      // +16*mf
    int aKoff = lane >> 4;                      // granule +0/1
    int wRow  = (lane & 7) + ((lane >> 4) << 3);
    int wKoff = (lane >> 3) & 1;

    const __nv_bfloat16* wth = g_wth[layer];
    const __nv_bfloat16* wtl = g_wtl[layer];

    #pragma unroll 1
    for (int kc = 0; kc < 2; kc++) {
        __syncthreads();   // A ready (kc=0) / prev compute done (kc=1)
        // ---- load W chunk (hi + lo), 4096 uint4 ----
        for (int i = tid; i < 4096; i += 256) {
            int half = i >> 11;
            int j = i & 2047;
            int r  = j >> 4;             // n row
            int kin = (j & 15) * 8;
            int s2 = kin >> 6;
            int gin = (kin >> 3) & 7;
            const __nv_bfloat16* base = half ? wtl : wth;
            uint4 v = __ldg((const uint4*)(base + (size_t)r * 256 + kc * 128 + kin));
            *(uint4*)(smem + SM_W + half * 32768 + s2 * 16384 + r * 128 +
                      ((gin ^ (r & 7)) * 16)) = v;
        }
        __syncthreads();

        #pragma unroll 1
        for (int ksl = 0; ksl < 8; ksl++) {
            int ks   = kc * 8 + ksl;
            int sA   = ks >> 2;
            int kgA  = (ks & 3) * 2 + aKoff;        // granule in 64-col section
            int s2   = ksl >> 2;
            int kgW  = (ksl & 3) * 2 + wKoff;

            #pragma unroll
            for (int ah = 0; ah < 2; ah++) {
                uint32_t af[2][4];
                #pragma unroll
                for (int mf = 0; mf < 2; mf++) {
                    int r = m0 + mf * 16 + aRow;
                    uint32_t addr = sb + SM_A + ah * 65536 + sA * 16384 +
                                    r * 128 + ((kgA ^ lx) * 16);
                    ldm4(af[mf], addr);
                }
                int nwh = (ah == 0) ? 2 : 1;        // Ah*{Wh,Wl}, Al*Wh
                #pragma unroll
                for (int wh = 0; wh < 2; wh++) {
                    if (wh >= nwh) break;
                    #pragma unroll
                    for (int np = 0; np < 4; np++) {
                        uint32_t wf[4];
                        int r = n0 + np * 16 + wRow;
                        uint32_t addr = sb + SM_W + wh * 32768 + s2 * 16384 +
                                        r * 128 + ((kgW ^ lx) * 16);
                        ldm4(wf, addr);
                        #pragma unroll
                        for (int mf = 0; mf < 2; mf++) {
                            mma16816(acc[mf][np * 2],     af[mf], wf[0], wf[1]);
                            mma16816(acc[mf][np * 2 + 1], af[mf], wf[2], wf[3]);
                        }
                    }
                }
            }
        }
    }

    // ---- epilogue: add bias, store fp32, fused BN column stats ----
    #pragma unroll
    for (int nf = 0; nf < 8; nf++) {
        int col = n0 + nf * 8 + (lane & 3) * 2;
        float bx = __ldg(&bias[col]), by = __ldg(&bias[col + 1]);
        float s0 = 0.f, q0 = 0.f, s1 = 0.f, q1 = 0.f;
        #pragma unroll
        for (int mf = 0; mf < 2; mf++) {
            int row = row0 + m0 + mf * 16 + (lane >> 2);
            if (row < n) {
                float a = acc[mf][nf][0] + bx, b = acc[mf][nf][1] + by;
                *(float2*)(g_hpre + (size_t)row * 128 + col) = make_float2(a, b);
                s0 += a; q0 += a * a; s1 += b; q1 += b * b;
            }
            if (row + 8 < n) {
                float a = acc[mf][nf][2] + bx, b = acc[mf][nf][3] + by;
                *(float2*)(g_hpre + (size_t)(row + 8) * 128 + col) = make_float2(a, b);
                s0 += a; q0 += a * a; s1 += b; q1 += b * b;
            }
        }
        #pragma unroll
        for (int off = 4; off < 32; off <<= 1) {
            s0 += __shfl_xor_sync(0xffffffffu, s0, off);
            q0 += __shfl_xor_sync(0xffffffffu, q0, off);
            s1 += __shfl_xor_sync(0xffffffffu, s1, off);
            q1 += __shfl_xor_sync(0xffffffffu, q1, off);
        }
        if (lane < 4) {
            int c = n0 + nf * 8 + lane * 2;
            atomicAdd(&g_stats[c],       s0);
            atomicAdd(&g_stats[128 + c], q0);
            atomicAdd(&g_stats[c + 1],       s1);
            atomicAdd(&g_stats[128 + c + 1], q1);
        }
    }
}

// ---------------- BatchNorm finalize ----------------
__global__ void k_finalize(const float* __restrict__ gamma,
                           const float* __restrict__ beta, int n) {
    int t = threadIdx.x;
    float invn = 1.0f / (float)n;
    float mu  = g_stats[t] * invn;
    float var = fmaxf(g_stats[128 + t] * invn - mu * mu, 0.f);
    float rs = rsqrtf(var + 1e-5f);
    float sc = __ldg(&gamma[t]) * rs;
    g_scale[t] = sc;
    g_shift[t] = __ldg(&beta[t]) - mu * sc;
}

// BN apply + ReLU -> g_h0 (fp32) + bf16 hi/lo; block 0 re-zeroes g_stats
__global__ void k_apply_relu(int n) {
    if (blockIdx.x == 0 && threadIdx.x < 256) g_stats[threadIdx.x] = 0.f;
    int n4 = n * 32;
    for (int i = blockIdx.x * blockDim.x + threadIdx.x; i < n4;
         i += gridDim.x * blockDim.x) {
        int cg = i & 31;
        float4 v  = ((const float4*)g_hpre)[i];
        float4 sc = ((const float4*)g_scale)[cg];
        float4 sh = ((const float4*)g_shift)[cg];
        v.x = fmaxf(v.x * sc.x + sh.x, 0.f);
        v.y = fmaxf(v.y * sc.y + sh.y, 0.f);
        v.z = fmaxf(v.z * sc.z + sh.z, 0.f);
        v.w = fmaxf(v.w * sc.w + sh.w, 0.f);
        ((float4*)g_h0)[i] = v;
        split4(v, g_h0h + (size_t)i * 4, g_h0l + (size_t)i * 4);
    }
}

// BN apply + ReLU + [128,2] linear -> d_out
__global__ void k_apply_out(const float* __restrict__ Wout,
                            const float* __restrict__ bout,
                            float* __restrict__ out, int n) {
    int gw   = (blockIdx.x * blockDim.x + threadIdx.x) >> 5;
    int lane = threadIdx.x & 31;
    if (gw >= n) return;
    float4 v  = ((const float4*)g_hpre)[gw * 32 + lane];
    float4 sc = ((const float4*)g_scale)[lane];
    float4 sh = ((const float4*)g_shift)[lane];
    v.x = fmaxf(v.x * sc.x + sh.x, 0.f);
    v.y = fmaxf(v.y * sc.y + sh.y, 0.f);
    v.z = fmaxf(v.z * sc.z + sh.z, 0.f);
    v.w = fmaxf(v.w * sc.w + sh.w, 0.f);
    const float4* W4 = (const float4*)Wout;
    float4 wa = __ldg(&W4[lane * 2]);
    float4 wb = __ldg(&W4[lane * 2 + 1]);
    float s0 = v.x * wa.x + v.y * wa.z + v.z * wb.x + v.w * wb.z;
    float s1 = v.x * wa.y + v.y * wa.w + v.z * wb.y + v.w * wb.w;
    #pragma unroll
    for (int off = 16; off; off >>= 1) {
        s0 += __shfl_xor_sync(0xffffffffu, s0, off);
        s1 += __shfl_xor_sync(0xffffffffu, s1, off);
    }
    if (lane == 0) {
        out[gw * 2 + 0] = s0 + __ldg(&bout[0]);
        out[gw * 2 + 1] = s1 + __ldg(&bout[1]);
    }
}

// ---------------------------------------------------------------------------
extern "C" void kernel_launch(void* const* d_in, const int* in_sizes, int n_in,
                              void* d_out, int out_size) {
    const float* x    = (const float*)d_in[0];
    const void*  ei   = d_in[1];
    const float* Wl0  = (const float*)d_in[2];
    const float* Wr0  = (const float*)d_in[3];
    const float* b0   = (const float*)d_in[4];
    const float* gm0  = (const float*)d_in[5];
    const float* be0  = (const float*)d_in[6];
    const float* Wl1  = (const float*)d_in[7];
    const float* Wr1  = (const float*)d_in[8];
    const float* b1   = (const float*)d_in[9];
    const float* gm1  = (const float*)d_in[10];
    const float* be1  = (const float*)d_in[11];
    const float* Wout = (const float*)d_in[12];
    const float* bout = (const float*)d_in[13];
    float* out = (float*)d_out;

    int E = in_sizes[1] / 2;  if (E > MAXE) E = MAXE;
    int n = out_size / 2;     if (n > MAXN) n = MAXN;

    cudaFuncSetAttribute(k_gemm_mma,
        cudaFuncAttributeMaxDynamicSharedMemorySize, SM_TOTAL);

    int eb = (E + 255) / 256;
    int nb = (n + 255) / 256;
    int ab = (n * 32 + 255) / 256;          // warp-per-node / float4-per-thread
    int gb = (n + 127) / 128;
    int sb = (n + 2047) / 2048;             // scan blocks

    // --- CSR build + splits ---
    k_detect    <<<1, 32>>>(ei, E);
    k_zero_build<<<nb, 256>>>(n);
    k_edges     <<<eb, 256>>>(ei, E);
    k_scan1     <<<sb, 256>>>(n);
    k_scan2     <<<1, 32>>>(sb);
    k_scan3     <<<nb, 256>>>(n);
    k_fill      <<<eb, 256>>>(E);
    k_split_x   <<<ab, 256>>>(x, n);
    k_prep_w    <<<128, 256>>>(Wl0, Wr0, 0);
    k_prep_w    <<<128, 256>>>(Wl1, Wr1, 1);

    // --- layer 0 ---
    k_aggregate <<<ab, 256>>>(x, 0, n);
    k_gemm_mma  <<<gb, 256, SM_TOTAL>>>(0, 1, b0, n);
    k_finalize  <<<1, 128>>>(gm0, be0, n);
    k_apply_relu<<<2048, 256>>>(n);

    // --- layer 1 ---
    k_aggregate <<<ab, 256>>>(nullptr, 1, n);
    k_gemm_mma  <<<gb, 256, SM_TOTAL>>>(1, 0, b1, n);
    k_finalize  <<<1, 128>>>(gm1, be1, n);

    // --- fused BN+ReLU+Linear[128->2] -> d_out ---
    k_apply_out <<<ab, 256>>>(Wout, bout, out, n);
}